// round 13
// baseline (speedup 1.0000x reference)
#include <cuda_runtime.h>
#include <cuda_bf16.h>
#include <cstdint>

#define BATCH 4096
#define NN 17
#define DIM 512
#define OUTC 3
#define KP 1536   // logical packed K = [hi|lo|hi] x 512
#define KPS 1024  // stored K = [hi|lo]

// ----------------------------- device scratch ------------------------------
__device__ __align__(16) __nv_bfloat16 g_Ap[(size_t)BATCH * KPS];  // [Ahi|Alo]
__device__ __align__(16) __nv_bfloat16 g_Bp[(size_t)DIM * KPS];    // [Bhi|Blo] (B^T rows)
__device__ __align__(16) float g_scale[(size_t)BATCH * DIM];
__device__ float g_P1T[9 * DIM];
__device__ float g_C3[9];
__device__ float g_T3[(size_t)BATCH * 9];
__device__ float g_L[NN * NN];
__device__ float g_Q[NN * NN];

__device__ __forceinline__ float silu_f(float v) { return v / (1.f + __expf(-v)); }

__device__ __forceinline__ uint32_t smem_u32(const void* p) {
    uint32_t a;
    asm("{ .reg .u64 t; cvta.to.shared.u64 t, %1; cvt.u32.u64 %0, t; }" : "=r"(a) : "l"(p));
    return a;
}
__device__ __forceinline__ void cp16(uint32_t dst, const void* src) {
    asm volatile("cp.async.cg.shared.global [%0], [%1], 16;" :: "r"(dst), "l"(src));
}
#define CP_COMMIT() asm volatile("cp.async.commit_group;" ::: "memory")
#define CP_WAIT(n)  asm volatile("cp.async.wait_group %0;" :: "n"(n) : "memory")

__device__ __forceinline__ void ldmx4(uint32_t* r, uint32_t addr) {
    asm volatile("ldmatrix.sync.aligned.m8n8.x4.shared.b16 {%0,%1,%2,%3}, [%4];"
                 : "=r"(r[0]), "=r"(r[1]), "=r"(r[2]), "=r"(r[3]) : "r"(addr));
}
__device__ __forceinline__ void mma_bf16(float* c, const uint32_t* a, const uint32_t* b) {
    asm volatile(
        "mma.sync.aligned.m16n8k16.row.col.f32.bf16.bf16.f32 "
        "{%0,%1,%2,%3}, {%4,%5,%6,%7}, {%8,%9}, {%0,%1,%2,%3};"
        : "+f"(c[0]), "+f"(c[1]), "+f"(c[2]), "+f"(c[3])
        : "r"(a[0]), "r"(a[1]), "r"(a[2]), "r"(a[3]), "r"(b[0]), "r"(b[1]));
}

// -------- packed f32x2 (PTX ISA 8.6, sm_100+ baseline) ----------------------
typedef unsigned long long u64;
union F2 { float2 f; u64 u; };
__device__ __forceinline__ u64 pack2(float a, float b) {
    F2 t; t.f = make_float2(a, b); return t.u;
}
#define FMA2(acc, a, b)   asm("fma.rn.f32x2 %0, %1, %2, %0;" : "+l"(acc) : "l"(a), "l"(b))
#define MUL2(d, a, b)     asm("mul.rn.f32x2 %0, %1, %2;"     : "=l"(d)  : "l"(a), "l"(b))
#define ADD2(acc, a)      asm("add.rn.f32x2 %0, %0, %1;"     : "+l"(acc) : "l"(a))

// ---------------------------------------------------------------------------
// setup: blocks 0..64 -> P1^T (+C3); block 65 -> L,Q; blocks 66..321 -> W2^T
// ---------------------------------------------------------------------------
__global__ __launch_bounds__(256) void setup_kernel(const float* __restrict__ Wmod,
                                                    const float* __restrict__ bmod,
                                                    const float* __restrict__ Wg,
                                                    const float* __restrict__ adj) {
    const int tid = threadIdx.x;
    const int bid = blockIdx.x;
    if (bid >= 66) {
        __shared__ float tile[32][33];
        int id = bid - 66;
        int n0 = (id & 15) * 32, k0 = (id >> 4) * 32;
        int tx = tid & 31, ty8 = tid >> 5;
        #pragma unroll
        for (int i = 0; i < 4; i++) {
            int r = ty8 + i * 8;
            tile[r][tx] = Wmod[(size_t)(k0 + r) * (2 * DIM) + DIM + n0 + tx];
        }
        __syncthreads();
        #pragma unroll
        for (int i = 0; i < 4; i++) {
            int r = ty8 + i * 8;
            float v = tile[tx][r];
            __nv_bfloat16 h = __float2bfloat16(v);
            size_t base = (size_t)(n0 + r) * KPS + (k0 + tx);
            g_Bp[base]       = h;
            g_Bp[base + 512] = __float2bfloat16(v - __bfloat162float(h));
        }
        return;
    }
    if (bid == 65) {
        __shared__ float sD[NN];
        __shared__ float sL[NN * NN];
        if (tid < NN) {
            float s = 0.f;
            #pragma unroll
            for (int m = 0; m < NN; m++) s += adj[tid * NN + m];
            sD[tid] = rsqrtf(s);
        }
        __syncthreads();
        for (int i = tid; i < NN * NN; i += 256) {
            int n = i / NN, m = i % NN;
            float v = ((n == m) ? 1.f : 0.f) - sD[n] * adj[i] * sD[m];
            sL[i] = v; g_L[i] = v;
        }
        __syncthreads();
        for (int i = tid; i < NN * NN; i += 256) {
            int n = i / NN, m = i % NN;
            float s = 0.f;
            #pragma unroll
            for (int j = 0; j < NN; j++) s += sL[n * NN + j] * sL[j * NN + m];
            g_Q[i] = 2.f * s - ((n == m) ? 1.f : 0.f);
        }
        return;
    }
    __shared__ float sWgT[9][DIM];
    const int w = tid >> 5, l = tid & 31;
    for (int i = tid; i < 9 * DIM; i += 256) {
        int k = i / (DIM * 3), r = i % (DIM * 3), c = r / 3, o = r % 3;
        sWgT[k * 3 + o][c] = Wg[i];
    }
    __syncthreads();
    int d = bid * 8 + w;
    if (d > DIM) return;
    float acc[9];
    #pragma unroll
    for (int t = 0; t < 9; t++) acc[t] = 0.f;
    #pragma unroll
    for (int j = 0; j < 4; j++) {
        int idx = j * 32 + l;
        float4 wv = (d < DIM)
            ? reinterpret_cast<const float4*>(Wmod + (size_t)d * 2 * DIM)[idx]
            : reinterpret_cast<const float4*>(bmod)[idx];
        #pragma unroll
        for (int t = 0; t < 9; t++) {
            float4 p = reinterpret_cast<const float4*>(sWgT[t])[idx];
            acc[t] += wv.x * p.x + wv.y * p.y + wv.z * p.z + wv.w * p.w;
        }
    }
    #pragma unroll
    for (int t = 0; t < 9; t++) {
        float a = acc[t];
        #pragma unroll
        for (int off = 16; off; off >>= 1) a += __shfl_xor_sync(0xffffffffu, a, off);
        if (l == 0) {
            if (d < DIM) g_P1T[t * DIM + d] = a;
            else         g_C3[t] = a;
        }
    }
}

// ---------------------------------------------------------------------------
// prep_c: fused silu(c) -> bf16 hi/lo [hi|lo] A' write  +  t3 dot products
// ---------------------------------------------------------------------------
__global__ __launch_bounds__(256) void prep_c(const float* __restrict__ cin) {
    __shared__ float sP[9][DIM];
    __shared__ float sC[9];
    const int tid = threadIdx.x, w = tid >> 5, l = tid & 31;
    for (int i = tid; i < 9 * DIM; i += 256) (&sP[0][0])[i] = g_P1T[i];
    if (tid < 9) sC[tid] = g_C3[tid];
    __syncthreads();
    const int b = blockIdx.x * 8 + w;
    float acc[9];
    #pragma unroll
    for (int t = 0; t < 9; t++) acc[t] = 0.f;
    const float4* cv = reinterpret_cast<const float4*>(cin + (size_t)b * DIM);
    __nv_bfloat16* ap = g_Ap + (size_t)b * KPS;
    #pragma unroll
    for (int j = 0; j < 4; j++) {
        int idx = j * 32 + l;
        float4 v = cv[idx];
        float s[4] = { silu_f(v.x), silu_f(v.y), silu_f(v.z), silu_f(v.w) };
        union U { __nv_bfloat16 b[4]; uint2 u; } hi, lo;
        #pragma unroll
        for (int e = 0; e < 4; e++) {
            __nv_bfloat16 h = __float2bfloat16(s[e]);
            hi.b[e] = h;
            lo.b[e] = __float2bfloat16(s[e] - __bfloat162float(h));
        }
        int kb = idx * 4;
        *reinterpret_cast<uint2*>(ap + kb)       = hi.u;
        *reinterpret_cast<uint2*>(ap + 512 + kb) = lo.u;
        #pragma unroll
        for (int t = 0; t < 9; t++) {
            float4 p = reinterpret_cast<const float4*>(sP[t])[idx];
            acc[t] += s[0] * p.x + s[1] * p.y + s[2] * p.z + s[3] * p.w;
        }
    }
    #pragma unroll
    for (int t = 0; t < 9; t++) {
        float a = acc[t];
        #pragma unroll
        for (int off = 16; off; off >>= 1) a += __shfl_xor_sync(0xffffffffu, a, off);
        if (l == 0) g_T3[(size_t)b * 9 + t] = a + sC[t];
    }
}

// ---------------------------------------------------------------------------
// scale GEMM (R12 config): CTA 128x128, 8 warps, 4-stage cp.async,
// fragment double-buffering, segment-mapped [hi|lo] storage.
// ---------------------------------------------------------------------------
#define TM 128
#define TN 128
#define TK 64
#define NSTAGE 4
#define A_ST_B (TM * TK * 2)
#define B_ST_B (TN * TK * 2)
#define STAGE_B (A_ST_B + B_ST_B)
#define GSMEM (STAGE_B * NSTAGE)

__global__ __launch_bounds__(256, 1) void scale_gemm(const float* __restrict__ bmod) {
    extern __shared__ __align__(128) char sm[];
    const uint32_t sbase = smem_u32(sm);
    const int tid = threadIdx.x;
    const int wid = tid >> 5, l = tid & 31;
    const int wm = wid >> 1, wn = wid & 1;
    const int m0 = blockIdx.x * TM, n0 = blockIdx.y * TN;

    auto load_stage = [&](int st, int chunk) {
        uint32_t abase = sbase + st * STAGE_B;
        uint32_t bbase = abase + A_ST_B;
        int k0 = chunk * TK;
        int ka = (k0 >= 1024) ? k0 - 1024 : k0;        // A: [hi|lo|hi]
        int kb = (k0 >= 512)  ? k0 - 512  : k0;        // B: [hi|hi|lo]
        #pragma unroll
        for (int i = 0; i < 4; i++) {
            int id = tid + i * 256;
            int row = id >> 3, kc = id & 7;
            uint32_t dst = abase + row * 128 + ((kc ^ (row & 7)) << 4);
            cp16(dst, g_Ap + (size_t)(m0 + row) * KPS + ka + kc * 8);
        }
        #pragma unroll
        for (int i = 0; i < 4; i++) {
            int id = tid + i * 256;
            int row = id >> 3, kc = id & 7;
            uint32_t dst = bbase + row * 128 + ((kc ^ (row & 7)) << 4);
            cp16(dst, g_Bp + (size_t)(n0 + row) * KPS + kb + kc * 8);
        }
    };

    float acc[2][8][4];
    #pragma unroll
    for (int mt = 0; mt < 2; mt++)
        #pragma unroll
        for (int nt = 0; nt < 8; nt++)
            #pragma unroll
            for (int e = 0; e < 4; e++) acc[mt][nt][e] = 0.f;

    #pragma unroll
    for (int s = 0; s < 3; s++) { load_stage(s, s); CP_COMMIT(); }

    const int NCHUNK = KP / TK;            // 24
    for (int it = 0; it < NCHUNK; ++it) {
        CP_WAIT(2);
        __syncthreads();
        if (it + 3 < NCHUNK) load_stage((it + 3) & 3, it + 3);
        CP_COMMIT();
        uint32_t abase = sbase + (it & 3) * STAGE_B;
        uint32_t bbase = abase + A_ST_B;

        uint32_t a[2][2][4], b[2][4][4];
        auto load_frags = [&](int slot, int kk) {
            int kc0 = kk * 2 + (l >> 4);
            #pragma unroll
            for (int mt = 0; mt < 2; mt++) {
                int row = wm * 32 + mt * 16 + (l & 15);
                ldmx4(a[slot][mt], abase + row * 128 + ((kc0 ^ (row & 7)) << 4));
            }
            #pragma unroll
            for (int g = 0; g < 4; g++) {
                int row = wn * 64 + g * 16 + (l & 15);
                ldmx4(b[slot][g], bbase + row * 128 + ((kc0 ^ (row & 7)) << 4));
            }
        };

        load_frags(0, 0);
        #pragma unroll
        for (int kk = 0; kk < 4; kk++) {
            const int cur = kk & 1;
            if (kk < 3) load_frags(cur ^ 1, kk + 1);
            #pragma unroll
            for (int mt = 0; mt < 2; mt++)
                #pragma unroll
                for (int g = 0; g < 4; g++) {
                    uint32_t b0[2] = { b[cur][g][0], b[cur][g][2] };
                    uint32_t b1[2] = { b[cur][g][1], b[cur][g][3] };
                    mma_bf16(acc[mt][2 * g],     a[cur][mt], b0);
                    mma_bf16(acc[mt][2 * g + 1], a[cur][mt], b1);
                }
        }
    }
    CP_WAIT(0);

    const int fr = l >> 2, fc = (l & 3) * 2;
    #pragma unroll
    for (int mt = 0; mt < 2; mt++) {
        int m = m0 + wm * 32 + mt * 16 + fr;
        #pragma unroll
        for (int nt = 0; nt < 8; nt++) {
            int n = n0 + wn * 64 + nt * 8 + fc;
            float2 bv = *reinterpret_cast<const float2*>(bmod + DIM + n);
            float2 v0 = make_float2(acc[mt][nt][0] + bv.x, acc[mt][nt][1] + bv.y);
            float2 v1 = make_float2(acc[mt][nt][2] + bv.x, acc[mt][nt][3] + bv.y);
            *reinterpret_cast<float2*>(g_scale + (size_t)m * DIM + n) = v0;
            *reinterpret_cast<float2*>(g_scale + (size_t)(m + 8) * DIM + n) = v1;
        }
    }
}

// ---------------------------------------------------------------------------
// final: BPB=1, 3 CTAs/SM (60.5 KB smem, reg budget 113).
// Single-pass u-trick; wv loaded inside t-loop (2 u64 live) to cut regs.
// ---------------------------------------------------------------------------
#define XROWS 18
#define XF (XROWS * DIM)              // 9216 floats
// smem layout (float offsets)
#define SM_WG 0                       // 4608
#define SM_L  (SM_WG + 9 * DIM)       // 4608
#define SM_Q  (SM_L + NN * NN)        // 4897
#define SM_T3 (SM_Q + NN * NN)        // 5186 [9]
#define SM_D  (SM_T3 + 9)             // 5195 [18][11][2] = 396
#define SM_Y  (SM_D + 18 * 11 * 2)    // 5591 [3][17][3] = 153
#define SM_X  5760                    // [18][512] (5760*4 % 16 == 0)
#define SM_SC (SM_X + XF)             // 14976 [512]
#define SM_F_TOT (SM_SC + DIM)        // 15488 floats
#define GSMEM_F (SM_F_TOT * 4)        // 61952 bytes

__global__ __launch_bounds__(192, 3) void final_kernel(const float* __restrict__ x,
                                                       const float* __restrict__ Wg,
                                                       const float* __restrict__ bg,
                                                       float* __restrict__ out) {
    extern __shared__ __align__(16) float sf[];
    const uint32_t sbase = smem_u32(sf);
    const int tid = threadIdx.x;
    const int w = tid >> 5;
    const int l = tid & 31;
    const int b = blockIdx.x;

    // stage x + scale first (DRAM latency overlapped with static staging)
    {
        const float* xp = x + (size_t)b * (NN * DIM);
        uint32_t dstx = sbase + SM_X * 4;
        #pragma unroll
        for (int i = 0; i < 12; i++) {
            int id = tid + i * 192;
            if (id < (NN * DIM) / 4) cp16(dstx + id * 16, xp + id * 4);
        }
        if (tid < DIM / 4)
            cp16(sbase + SM_SC * 4 + tid * 16, g_scale + (size_t)b * DIM + tid * 4);
        CP_COMMIT();
    }

    for (int i = tid; i < 9 * DIM; i += 192) {
        int k = i / (DIM * 3), r = i % (DIM * 3), c = r / 3, o = r % 3;
        sf[SM_WG + (k * 3 + o) * DIM + c] = Wg[i];
    }
    for (int i = tid; i < NN * NN; i += 192) {
        sf[SM_L + i] = g_L[i];
        sf[SM_Q + i] = g_Q[i];
    }
    for (int i = tid; i < DIM; i += 192)
        sf[SM_X + NN * DIM + i] = 1.f;      // ones row (slot 17 -> u_t)
    if (tid < 9) sf[SM_T3 + tid] = g_T3[(size_t)b * 9 + tid];

    CP_WAIT(0);
    __syncthreads();

    const float* sx  = sf + SM_X;
    const float* ssc = sf + SM_SC;

    // single pass: 9 dots + s + s2 per slot (slots = 3w+r, 0..17)
    u64 acc2[3][11];
    #pragma unroll
    for (int r = 0; r < 3; r++)
        #pragma unroll
        for (int t = 0; t < 11; t++) acc2[r][t] = 0ull;

    #pragma unroll
    for (int j = 0; j < 4; j++) {
        const int idx = j * 32 + l;
        float4 sc = reinterpret_cast<const float4*>(ssc)[idx];
        u64 g01 = pack2(sc.x + 1.f, sc.y + 1.f);
        u64 g23 = pack2(sc.z + 1.f, sc.w + 1.f);
        u64 xm01[3], xm23[3];
        #pragma unroll
        for (int r = 0; r < 3; r++) {
            const int n = w * 3 + r;
            float4 v = reinterpret_cast<const float4*>(sx + n * DIM)[idx];
            u64 v01 = pack2(v.x, v.y), v23 = pack2(v.z, v.w);
            MUL2(xm01[r], v01, g01);
            MUL2(xm23[r], v23, g23);
            ADD2(acc2[r][9], v01); ADD2(acc2[r][9], v23);              // s
            FMA2(acc2[r][10], v01, v01); FMA2(acc2[r][10], v23, v23);  // s2
        }
        #pragma unroll
        for (int t = 0; t < 9; t++) {
            float4 wv = reinterpret_cast<const float4*>(sf + SM_WG + t * DIM)[idx];
            u64 wv01 = pack2(wv.x, wv.y);
            u64 wv23 = pack2(wv.z, wv.w);
            #pragma unroll
            for (int r = 0; r < 3; r++) {
                FMA2(acc2[r][t], xm01[r], wv01);
                FMA2(acc2[r][t], xm23[r], wv23);
            }
        }
    }

    // 4-step butterfly -> 2 partials, lanes 0-1 write
    #pragma unroll
    for (int r = 0; r < 3; r++) {
        const int n = w * 3 + r;
        #pragma unroll
        for (int t = 0; t < 11; t++) {
            F2 u; u.u = acc2[r][t];
            float a = u.f.x + u.f.y;
            a += __shfl_xor_sync(0xffffffffu, a, 16);
            a += __shfl_xor_sync(0xffffffffu, a, 8);
            a += __shfl_xor_sync(0xffffffffu, a, 4);
            a += __shfl_xor_sync(0xffffffffu, a, 2);
            if (l < 2)
                sf[SM_D + (n * 11 + t) * 2 + l] = a;
        }
    }
    __syncthreads();

    // phase A: y[k][n][o] = rstd*(d - mu*u)
    if (tid < 153) {
        int k = tid / 51, rr = tid % 51, n = rr / 3, o = rr % 3;
        int t = k * 3 + o;
        const float* dbase = sf + SM_D + (n * 11) * 2;
        const float* ubase = sf + SM_D + (17 * 11) * 2;
        float d = dbase[t * 2] + dbase[t * 2 + 1];
        float u = ubase[t * 2] + ubase[t * 2 + 1];
        float s  = dbase[9 * 2]  + dbase[9 * 2 + 1];
        float s2 = dbase[10 * 2] + dbase[10 * 2 + 1];
        float mu = s * (1.f / DIM);
        float var = s2 * (1.f / DIM) - mu * mu;
        float rstd = rsqrtf(var + 1e-6f);
        sf[SM_Y + (k * NN + n) * OUTC + o] = rstd * (d - mu * u);
    }
    __syncthreads();

    // phase B: graph combine + t3 + bias
    if (tid < NN * OUTC) {
        int n = tid / OUTC, o = tid - n * OUTC;
        const float* t3 = sf + SM_T3;
        const float* y0 = sf + SM_Y;
        const float* y1 = sf + SM_Y + NN * OUTC;
        const float* y2 = sf + SM_Y + 2 * NN * OUTC;
        float t31 = t3[3 + o], t32 = t3[6 + o];
        float res = y0[n * OUTC + o] + t3[o] + bg[o];
        #pragma unroll
        for (int m = 0; m < NN; m++)
            res += sf[SM_L + n * NN + m] * (y1[m * OUTC + o] + t31)
                 + sf[SM_Q + n * NN + m] * (y2[m * OUTC + o] + t32);
        out[((size_t)b * NN + n) * OUTC + o] = res;
    }
}

// ---------------------------------------------------------------------------
extern "C" void kernel_launch(void* const* d_in, const int* in_sizes, int n_in,
                              void* d_out, int out_size) {
    const float* x     = (const float*)d_in[0];  // [4096,17,512]
    const float* adj   = (const float*)d_in[1];  // [17,17]
    const float* c     = (const float*)d_in[2];  // [4096,1,512]
    const float* W_mod = (const float*)d_in[3];  // [512,1024]
    const float* b_mod = (const float*)d_in[4];  // [1024]
    const float* Wg    = (const float*)d_in[5];  // [3,512,3]
    const float* bg    = (const float*)d_in[6];  // [3]
    float* out = (float*)d_out;                  // [4096,17,3] f32

    cudaFuncSetAttribute(scale_gemm, cudaFuncAttributeMaxDynamicSharedMemorySize, GSMEM);
    cudaFuncSetAttribute(final_kernel, cudaFuncAttributeMaxDynamicSharedMemorySize, GSMEM_F);

    setup_kernel<<<322, 256>>>(W_mod, b_mod, Wg, adj);
    prep_c<<<BATCH / 8, 256>>>(c);
    scale_gemm<<<dim3(BATCH / TM, DIM / TN), 256, GSMEM>>>(b_mod);
    final_kernel<<<BATCH, 192, GSMEM_F>>>(x, Wg, bg, out);
}

// round 14
// speedup vs baseline: 1.0901x; 1.0901x over previous
#include <cuda_runtime.h>
#include <cuda_bf16.h>
#include <cstdint>

#define BATCH 4096
#define NN 17
#define DIM 512
#define OUTC 3
#define KP 1536   // logical packed K = [hi|lo|hi] x 512
#define KPS 1024  // stored K = [hi|lo]

// ----------------------------- device scratch ------------------------------
__device__ __align__(16) __nv_bfloat16 g_Ap[(size_t)BATCH * KPS];  // [Ahi|Alo]
__device__ __align__(16) __nv_bfloat16 g_Bp[(size_t)DIM * KPS];    // [Bhi|Blo]
__device__ __align__(16) float g_scale[(size_t)BATCH * DIM];
__device__ float g_P1T[9 * DIM];
__device__ float g_C3[9];
__device__ float g_T3[(size_t)BATCH * 9];
__device__ __align__(16) float g_WgT[9 * DIM];   // [t][c]
__device__ __align__(16) float g_LQ[592];        // L @0 (289), Q @296 (289), padded

__device__ __forceinline__ float silu_f(float v) { return v / (1.f + __expf(-v)); }

__device__ __forceinline__ uint32_t smem_u32(const void* p) {
    uint32_t a;
    asm("{ .reg .u64 t; cvta.to.shared.u64 t, %1; cvt.u32.u64 %0, t; }" : "=r"(a) : "l"(p));
    return a;
}
__device__ __forceinline__ void cp16(uint32_t dst, const void* src) {
    asm volatile("cp.async.cg.shared.global [%0], [%1], 16;" :: "r"(dst), "l"(src));
}
#define CP_COMMIT() asm volatile("cp.async.commit_group;" ::: "memory")
#define CP_WAIT(n)  asm volatile("cp.async.wait_group %0;" :: "n"(n) : "memory")

__device__ __forceinline__ void ldmx4(uint32_t* r, uint32_t addr) {
    asm volatile("ldmatrix.sync.aligned.m8n8.x4.shared.b16 {%0,%1,%2,%3}, [%4];"
                 : "=r"(r[0]), "=r"(r[1]), "=r"(r[2]), "=r"(r[3]) : "r"(addr));
}
__device__ __forceinline__ void mma_bf16(float* c, const uint32_t* a, const uint32_t* b) {
    asm volatile(
        "mma.sync.aligned.m16n8k16.row.col.f32.bf16.bf16.f32 "
        "{%0,%1,%2,%3}, {%4,%5,%6,%7}, {%8,%9}, {%0,%1,%2,%3};"
        : "+f"(c[0]), "+f"(c[1]), "+f"(c[2]), "+f"(c[3])
        : "r"(a[0]), "r"(a[1]), "r"(a[2]), "r"(a[3]), "r"(b[0]), "r"(b[1]));
}

// -------- packed f32x2 ------------------------------------------------------
typedef unsigned long long u64;
union F2 { float2 f; u64 u; };
__device__ __forceinline__ u64 pack2(float a, float b) {
    F2 t; t.f = make_float2(a, b); return t.u;
}
#define FMA2(acc, a, b)   asm("fma.rn.f32x2 %0, %1, %2, %0;" : "+l"(acc) : "l"(a), "l"(b))
#define MUL2(d, a, b)     asm("mul.rn.f32x2 %0, %1, %2;"     : "=l"(d)  : "l"(a), "l"(b))
#define ADD2(acc, a)      asm("add.rn.f32x2 %0, %0, %1;"     : "+l"(acc) : "l"(a))

// ---------------------------------------------------------------------------
// setup: blocks 0..64 -> P1^T (+C3); block 65 -> L,Q (g_LQ) + g_WgT;
//        blocks 66..321 -> W2^T hi/lo
// ---------------------------------------------------------------------------
__global__ __launch_bounds__(256) void setup_kernel(const float* __restrict__ Wmod,
                                                    const float* __restrict__ bmod,
                                                    const float* __restrict__ Wg,
                                                    const float* __restrict__ adj) {
    const int tid = threadIdx.x;
    const int bid = blockIdx.x;
    if (bid >= 66) {
        __shared__ float tile[32][33];
        int id = bid - 66;
        int n0 = (id & 15) * 32, k0 = (id >> 4) * 32;
        int tx = tid & 31, ty8 = tid >> 5;
        #pragma unroll
        for (int i = 0; i < 4; i++) {
            int r = ty8 + i * 8;
            tile[r][tx] = Wmod[(size_t)(k0 + r) * (2 * DIM) + DIM + n0 + tx];
        }
        __syncthreads();
        #pragma unroll
        for (int i = 0; i < 4; i++) {
            int r = ty8 + i * 8;
            float v = tile[tx][r];
            __nv_bfloat16 h = __float2bfloat16(v);
            size_t base = (size_t)(n0 + r) * KPS + (k0 + tx);
            g_Bp[base]       = h;
            g_Bp[base + 512] = __float2bfloat16(v - __bfloat162float(h));
        }
        return;
    }
    if (bid == 65) {
        __shared__ float sD[NN];
        __shared__ float sL[NN * NN];
        if (tid < NN) {
            float s = 0.f;
            #pragma unroll
            for (int m = 0; m < NN; m++) s += adj[tid * NN + m];
            sD[tid] = rsqrtf(s);
        }
        __syncthreads();
        for (int i = tid; i < NN * NN; i += 256) {
            int n = i / NN, m = i % NN;
            float v = ((n == m) ? 1.f : 0.f) - sD[n] * adj[i] * sD[m];
            sL[i] = v; g_LQ[i] = v;
        }
        __syncthreads();
        for (int i = tid; i < NN * NN; i += 256) {
            int n = i / NN, m = i % NN;
            float s = 0.f;
            #pragma unroll
            for (int j = 0; j < NN; j++) s += sL[n * NN + j] * sL[j * NN + m];
            g_LQ[296 + i] = 2.f * s - ((n == m) ? 1.f : 0.f);
        }
        // transposed Wg for cheap final staging
        for (int i = tid; i < 9 * DIM; i += 256) {
            int k = i / (DIM * 3), r = i % (DIM * 3), c = r / 3, o = r % 3;
            g_WgT[(k * 3 + o) * DIM + c] = Wg[i];
        }
        return;
    }
    __shared__ float sWgT[9][DIM];
    const int w = tid >> 5, l = tid & 31;
    for (int i = tid; i < 9 * DIM; i += 256) {
        int k = i / (DIM * 3), r = i % (DIM * 3), c = r / 3, o = r % 3;
        sWgT[k * 3 + o][c] = Wg[i];
    }
    __syncthreads();
    int d = bid * 8 + w;
    if (d > DIM) return;
    float acc[9];
    #pragma unroll
    for (int t = 0; t < 9; t++) acc[t] = 0.f;
    #pragma unroll
    for (int j = 0; j < 4; j++) {
        int idx = j * 32 + l;
        float4 wv = (d < DIM)
            ? reinterpret_cast<const float4*>(Wmod + (size_t)d * 2 * DIM)[idx]
            : reinterpret_cast<const float4*>(bmod)[idx];
        #pragma unroll
        for (int t = 0; t < 9; t++) {
            float4 p = reinterpret_cast<const float4*>(sWgT[t])[idx];
            acc[t] += wv.x * p.x + wv.y * p.y + wv.z * p.z + wv.w * p.w;
        }
    }
    #pragma unroll
    for (int t = 0; t < 9; t++) {
        float a = acc[t];
        #pragma unroll
        for (int off = 16; off; off >>= 1) a += __shfl_xor_sync(0xffffffffu, a, off);
        if (l == 0) {
            if (d < DIM) g_P1T[t * DIM + d] = a;
            else         g_C3[t] = a;
        }
    }
}

// ---------------------------------------------------------------------------
// prep_c: fused silu(c) -> bf16 hi/lo [hi|lo] A' write  +  t3 dot products
// ---------------------------------------------------------------------------
__global__ __launch_bounds__(256) void prep_c(const float* __restrict__ cin) {
    __shared__ float sP[9][DIM];
    __shared__ float sC[9];
    const int tid = threadIdx.x, w = tid >> 5, l = tid & 31;
    for (int i = tid; i < 9 * DIM; i += 256) (&sP[0][0])[i] = g_P1T[i];
    if (tid < 9) sC[tid] = g_C3[tid];
    __syncthreads();
    const int b = blockIdx.x * 8 + w;
    float acc[9];
    #pragma unroll
    for (int t = 0; t < 9; t++) acc[t] = 0.f;
    const float4* cv = reinterpret_cast<const float4*>(cin + (size_t)b * DIM);
    __nv_bfloat16* ap = g_Ap + (size_t)b * KPS;
    #pragma unroll
    for (int j = 0; j < 4; j++) {
        int idx = j * 32 + l;
        float4 v = cv[idx];
        float s[4] = { silu_f(v.x), silu_f(v.y), silu_f(v.z), silu_f(v.w) };
        union U { __nv_bfloat16 b[4]; uint2 u; } hi, lo;
        #pragma unroll
        for (int e = 0; e < 4; e++) {
            __nv_bfloat16 h = __float2bfloat16(s[e]);
            hi.b[e] = h;
            lo.b[e] = __float2bfloat16(s[e] - __bfloat162float(h));
        }
        int kb = idx * 4;
        *reinterpret_cast<uint2*>(ap + kb)       = hi.u;
        *reinterpret_cast<uint2*>(ap + 512 + kb) = lo.u;
        #pragma unroll
        for (int t = 0; t < 9; t++) {
            float4 p = reinterpret_cast<const float4*>(sP[t])[idx];
            acc[t] += s[0] * p.x + s[1] * p.y + s[2] * p.z + s[3] * p.w;
        }
    }
    #pragma unroll
    for (int t = 0; t < 9; t++) {
        float a = acc[t];
        #pragma unroll
        for (int off = 16; off; off >>= 1) a += __shfl_xor_sync(0xffffffffu, a, off);
        if (l == 0) g_T3[(size_t)b * 9 + t] = a + sC[t];
    }
}

// ---------------------------------------------------------------------------
// scale GEMM (R12 config): CTA 128x128, 8 warps, 4-stage cp.async,
// fragment double-buffering, segment-mapped [hi|lo] storage.
// ---------------------------------------------------------------------------
#define TM 128
#define TN 128
#define TK 64
#define NSTAGE 4
#define A_ST_B (TM * TK * 2)
#define B_ST_B (TN * TK * 2)
#define STAGE_B (A_ST_B + B_ST_B)
#define GSMEM (STAGE_B * NSTAGE)

__global__ __launch_bounds__(256, 1) void scale_gemm(const float* __restrict__ bmod) {
    extern __shared__ __align__(128) char sm[];
    const uint32_t sbase = smem_u32(sm);
    const int tid = threadIdx.x;
    const int wid = tid >> 5, l = tid & 31;
    const int wm = wid >> 1, wn = wid & 1;
    const int m0 = blockIdx.x * TM, n0 = blockIdx.y * TN;

    auto load_stage = [&](int st, int chunk) {
        uint32_t abase = sbase + st * STAGE_B;
        uint32_t bbase = abase + A_ST_B;
        int k0 = chunk * TK;
        int ka = (k0 >= 1024) ? k0 - 1024 : k0;        // A: [hi|lo|hi]
        int kb = (k0 >= 512)  ? k0 - 512  : k0;        // B: [hi|hi|lo]
        #pragma unroll
        for (int i = 0; i < 4; i++) {
            int id = tid + i * 256;
            int row = id >> 3, kc = id & 7;
            uint32_t dst = abase + row * 128 + ((kc ^ (row & 7)) << 4);
            cp16(dst, g_Ap + (size_t)(m0 + row) * KPS + ka + kc * 8);
        }
        #pragma unroll
        for (int i = 0; i < 4; i++) {
            int id = tid + i * 256;
            int row = id >> 3, kc = id & 7;
            uint32_t dst = bbase + row * 128 + ((kc ^ (row & 7)) << 4);
            cp16(dst, g_Bp + (size_t)(n0 + row) * KPS + kb + kc * 8);
        }
    };

    float acc[2][8][4];
    #pragma unroll
    for (int mt = 0; mt < 2; mt++)
        #pragma unroll
        for (int nt = 0; nt < 8; nt++)
            #pragma unroll
            for (int e = 0; e < 4; e++) acc[mt][nt][e] = 0.f;

    #pragma unroll
    for (int s = 0; s < 3; s++) { load_stage(s, s); CP_COMMIT(); }

    const int NCHUNK = KP / TK;            // 24
    for (int it = 0; it < NCHUNK; ++it) {
        CP_WAIT(2);
        __syncthreads();
        if (it + 3 < NCHUNK) load_stage((it + 3) & 3, it + 3);
        CP_COMMIT();
        uint32_t abase = sbase + (it & 3) * STAGE_B;
        uint32_t bbase = abase + A_ST_B;

        uint32_t a[2][2][4], b[2][4][4];
        auto load_frags = [&](int slot, int kk) {
            int kc0 = kk * 2 + (l >> 4);
            #pragma unroll
            for (int mt = 0; mt < 2; mt++) {
                int row = wm * 32 + mt * 16 + (l & 15);
                ldmx4(a[slot][mt], abase + row * 128 + ((kc0 ^ (row & 7)) << 4));
            }
            #pragma unroll
            for (int g = 0; g < 4; g++) {
                int row = wn * 64 + g * 16 + (l & 15);
                ldmx4(b[slot][g], bbase + row * 128 + ((kc0 ^ (row & 7)) << 4));
            }
        };

        load_frags(0, 0);
        #pragma unroll
        for (int kk = 0; kk < 4; kk++) {
            const int cur = kk & 1;
            if (kk < 3) load_frags(cur ^ 1, kk + 1);
            #pragma unroll
            for (int mt = 0; mt < 2; mt++)
                #pragma unroll
                for (int g = 0; g < 4; g++) {
                    uint32_t b0[2] = { b[cur][g][0], b[cur][g][2] };
                    uint32_t b1[2] = { b[cur][g][1], b[cur][g][3] };
                    mma_bf16(acc[mt][2 * g],     a[cur][mt], b0);
                    mma_bf16(acc[mt][2 * g + 1], a[cur][mt], b1);
                }
        }
    }
    CP_WAIT(0);

    const int fr = l >> 2, fc = (l & 3) * 2;
    #pragma unroll
    for (int mt = 0; mt < 2; mt++) {
        int m = m0 + wm * 32 + mt * 16 + fr;
        #pragma unroll
        for (int nt = 0; nt < 8; nt++) {
            int n = n0 + wn * 64 + nt * 8 + fc;
            float2 bv = *reinterpret_cast<const float2*>(bmod + DIM + n);
            float2 v0 = make_float2(acc[mt][nt][0] + bv.x, acc[mt][nt][1] + bv.y);
            float2 v1 = make_float2(acc[mt][nt][2] + bv.x, acc[mt][nt][3] + bv.y);
            *reinterpret_cast<float2*>(g_scale + (size_t)m * DIM + n) = v0;
            *reinterpret_cast<float2*>(g_scale + (size_t)(m + 8) * DIM + n) = v1;
        }
    }
}

// ---------------------------------------------------------------------------
// final: R12 structure (BPB=4, measured best) with all staging via cp.async
// from precomputed g_WgT / g_LQ (no div/mod scatter).
// ---------------------------------------------------------------------------
#define BPB 4
#define XROWS 18
#define XF (XROWS * DIM)              // 9216 floats per buffer
// smem layout (float offsets)
#define SM_WG 0                       // 4608
#define SM_LQ (SM_WG + 9 * DIM)       // 4608 (592: L@+0, Q@+296)
#define SM_L  SM_LQ
#define SM_Q  (SM_LQ + 296)
#define SM_T3 (SM_LQ + 592)           // 5200 [4][9]
#define SM_D  (SM_T3 + 36)            // 5236 [4][18][11][2] = 1584
#define SM_Y  (SM_D + 1584)           // 6820 [4][3][17][3] = 612
#define SM_X  7440                    // 2 x 9216 (7440*4 % 16 == 0)
#define SM_SC (SM_X + 2 * XF)         // 25872 [2][512]
#define SM_F_TOT (SM_SC + 2 * DIM)    // 26896 floats
#define GSMEM_F (SM_F_TOT * 4)        // 107584 bytes

__global__ __launch_bounds__(192, 2) void final_kernel(const float* __restrict__ x,
                                                       const float* __restrict__ bg,
                                                       float* __restrict__ out) {
    extern __shared__ __align__(16) float sf[];
    const uint32_t sbase = smem_u32(sf);
    const int tid = threadIdx.x;
    const int w = tid >> 5;
    const int l = tid & 31;

    auto stage = [&](int bb, int buf) {
        const int b = blockIdx.x * BPB + bb;
        const float* xp = x + (size_t)b * (NN * DIM);
        uint32_t dstx = sbase + (SM_X + buf * XF) * 4;
        #pragma unroll
        for (int i = 0; i < 12; i++) {
            int id = tid + i * 192;
            if (id < (NN * DIM) / 4) cp16(dstx + id * 16, xp + id * 4);
        }
        if (tid < DIM / 4)
            cp16(sbase + (SM_SC + buf * DIM) * 4 + tid * 16,
                 g_scale + (size_t)b * DIM + tid * 4);
    };

    stage(0, 0); CP_COMMIT();

    // static staging: pure 16B cp.async from precomputed layouts
    #pragma unroll
    for (int i = 0; i < 6; i++) {                    // WgT: 1152 chunks
        int id = tid + i * 192;
        cp16(sbase + (SM_WG + id * 4) * 4, g_WgT + id * 4);
    }
    if (tid < 148)                                    // LQ: 148 chunks
        cp16(sbase + (SM_LQ + tid * 4) * 4, g_LQ + tid * 4);
    CP_COMMIT();

    // ones rows (slot 17 of both x buffers) -> u_t
    for (int i = tid; i < DIM; i += 192) {
        sf[SM_X + NN * DIM + i]      = 1.f;
        sf[SM_X + XF + NN * DIM + i] = 1.f;
    }

    for (int bb = 0; bb < BPB; ++bb) {
        const int b = blockIdx.x * BPB + bb;
        const int buf = bb & 1;
        CP_WAIT(0);
        __syncthreads();
        if (bb + 1 < BPB) { stage(bb + 1, buf ^ 1); CP_COMMIT(); }
        if (tid < 9) sf[SM_T3 + bb * 9 + tid] = g_T3[(size_t)b * 9 + tid];

        const float* sx  = sf + SM_X + buf * XF;
        const float* ssc = sf + SM_SC + buf * DIM;

        u64 acc2[3][11];
        #pragma unroll
        for (int r = 0; r < 3; r++)
            #pragma unroll
            for (int t = 0; t < 11; t++) acc2[r][t] = 0ull;

        #pragma unroll
        for (int j = 0; j < 4; j++) {
            const int idx = j * 32 + l;
            float4 sc = reinterpret_cast<const float4*>(ssc)[idx];
            u64 g01 = pack2(sc.x + 1.f, sc.y + 1.f);
            u64 g23 = pack2(sc.z + 1.f, sc.w + 1.f);
            u64 wv01[9], wv23[9];
            #pragma unroll
            for (int t = 0; t < 9; t++) {
                float4 wv = reinterpret_cast<const float4*>(sf + SM_WG + t * DIM)[idx];
                wv01[t] = pack2(wv.x, wv.y);
                wv23[t] = pack2(wv.z, wv.w);
            }
            #pragma unroll
            for (int r = 0; r < 3; r++) {
                const int n = w * 3 + r;
                float4 v = reinterpret_cast<const float4*>(sx + n * DIM)[idx];
                u64 v01 = pack2(v.x, v.y), v23 = pack2(v.z, v.w);
                u64 xm01, xm23;
                MUL2(xm01, v01, g01);
                MUL2(xm23, v23, g23);
                ADD2(acc2[r][9], v01); ADD2(acc2[r][9], v23);
                FMA2(acc2[r][10], v01, v01); FMA2(acc2[r][10], v23, v23);
                #pragma unroll
                for (int t = 0; t < 9; t++) {
                    FMA2(acc2[r][t], xm01, wv01[t]);
                    FMA2(acc2[r][t], xm23, wv23[t]);
                }
            }
        }

        #pragma unroll
        for (int r = 0; r < 3; r++) {
            const int n = w * 3 + r;
            #pragma unroll
            for (int t = 0; t < 11; t++) {
                F2 u; u.u = acc2[r][t];
                float a = u.f.x + u.f.y;
                a += __shfl_xor_sync(0xffffffffu, a, 16);
                a += __shfl_xor_sync(0xffffffffu, a, 8);
                a += __shfl_xor_sync(0xffffffffu, a, 4);
                a += __shfl_xor_sync(0xffffffffu, a, 2);
                if (l < 2)
                    sf[SM_D + (((bb * 18 + n) * 11) + t) * 2 + l] = a;
            }
        }
    }
    __syncthreads();

    // phase A: y[b][k][n][o] = rstd*(d - mu*u)
    for (int i = tid; i < 4 * 153; i += 192) {
        int b4 = i / 153, r = i % 153;
        int k = r / 51, rr = r % 51, n = rr / 3, o = rr % 3;
        int t = k * 3 + o;
        const float* dbase = sf + SM_D + ((b4 * 18 + n) * 11) * 2;
        const float* ubase = sf + SM_D + ((b4 * 18 + 17) * 11) * 2;
        float d = dbase[t * 2] + dbase[t * 2 + 1];
        float u = ubase[t * 2] + ubase[t * 2 + 1];
        float s  = dbase[9 * 2]  + dbase[9 * 2 + 1];
        float s2 = dbase[10 * 2] + dbase[10 * 2 + 1];
        float mu = s * (1.f / DIM);
        float var = s2 * (1.f / DIM) - mu * mu;
        float rstd = rsqrtf(var + 1e-6f);
        sf[SM_Y + ((b4 * 3 + k) * NN + n) * OUTC + o] = rstd * (d - mu * u);
    }
    __syncthreads();

    // phase B: graph combine + t3 + bias
    for (int i = tid; i < 4 * NN * OUTC; i += 192) {
        int b4 = i / (NN * OUTC), r = i % (NN * OUTC);
        int n = r / OUTC, o = r % OUTC;
        const int b = blockIdx.x * BPB + b4;
        const float* t3 = sf + SM_T3 + b4 * 9;
        const float* y0 = sf + SM_Y + (b4 * 3 + 0) * NN * OUTC;
        const float* y1 = sf + SM_Y + (b4 * 3 + 1) * NN * OUTC;
        const float* y2 = sf + SM_Y + (b4 * 3 + 2) * NN * OUTC;
        float t31 = t3[3 + o], t32 = t3[6 + o];
        float res = y0[n * OUTC + o] + t3[o] + bg[o];
        #pragma unroll
        for (int m = 0; m < NN; m++)
            res += sf[SM_L + n * NN + m] * (y1[m * OUTC + o] + t31)
                 + sf[SM_Q + n * NN + m] * (y2[m * OUTC + o] + t32);
        out[((size_t)b * NN + n) * OUTC + o] = res;
    }
}

// ---------------------------------------------------------------------------
extern "C" void kernel_launch(void* const* d_in, const int* in_sizes, int n_in,
                              void* d_out, int out_size) {
    const float* x     = (const float*)d_in[0];  // [4096,17,512]
    const float* adj   = (const float*)d_in[1];  // [17,17]
    const float* c     = (const float*)d_in[2];  // [4096,1,512]
    const float* W_mod = (const float*)d_in[3];  // [512,1024]
    const float* b_mod = (const float*)d_in[4];  // [1024]
    const float* Wg    = (const float*)d_in[5];  // [3,512,3]
    const float* bg    = (const float*)d_in[6];  // [3]
    float* out = (float*)d_out;                  // [4096,17,3] f32

    cudaFuncSetAttribute(scale_gemm, cudaFuncAttributeMaxDynamicSharedMemorySize, GSMEM);
    cudaFuncSetAttribute(final_kernel, cudaFuncAttributeMaxDynamicSharedMemorySize, GSMEM_F);

    setup_kernel<<<322, 256>>>(W_mod, b_mod, Wg, adj);
    prep_c<<<BATCH / 8, 256>>>(c);
    scale_gemm<<<dim3(BATCH / TM, DIM / TN), 256, GSMEM>>>(b_mod);
    final_kernel<<<BATCH / BPB, 192, GSMEM_F>>>(x, bg, out);
}